// round 15
// baseline (speedup 1.0000x reference)
#include <cuda_runtime.h>

#define TT 20
#define MM 6
#define MAXN 8192
typedef unsigned long long u64;

// scratch (allocation-free rule: __device__ globals)
__device__ __align__(16) float g_hidden[(size_t)TT * MAXN * MM * 12];
__device__ __align__(16) float g_lstm[2][(size_t)TT * MAXN * MM * 12];
__device__ int d_list[MAXN * MM];
__device__ int d_nvalid;

// ---------------- f32x2 helpers ----------------
__device__ __forceinline__ u64 pk(float a, float b) {
    u64 r; asm("mov.b64 %0, {%1, %2};" : "=l"(r) : "f"(a), "f"(b)); return r;
}
__device__ __forceinline__ void upk(float& a, float& b, u64 v) {
    asm("mov.b64 {%0, %1}, %2;" : "=f"(a), "=f"(b) : "l"(v));
}
__device__ __forceinline__ u64 ffma2(u64 a, u64 b, u64 c) {
    u64 r; asm("fma.rn.f32x2 %0, %1, %2, %3;" : "=l"(r) : "l"(a), "l"(b), "l"(c)); return r;
}

// ---------------- MUFU.TANH activations (proven: rel_err ~1.5e-6 end-to-end) ----------------
__device__ __forceinline__ float ftanh_fast(float x) {
    float t; asm("tanh.approx.f32 %0, %1;" : "=f"(t) : "f"(x));
    return t;
}
__device__ __forceinline__ float fsig_fast(float x) {
    float t; asm("tanh.approx.f32 %0, %1;" : "=f"(t) : "f"(0.5f * x));
    return fmaf(0.5f, t, 0.5f);
}

// ---------------- scalar dot helpers ----------------
__device__ __forceinline__ void load9(float* r, const float* __restrict__ p) {
    float4 a = *(const float4*)p;
    float4 b = *(const float4*)(p + 4);
    r[0]=a.x; r[1]=a.y; r[2]=a.z; r[3]=a.w;
    r[4]=b.x; r[5]=b.y; r[6]=b.z; r[7]=b.w;
    r[8]=p[8];
}

// ================= KC: deterministic compaction of valid (n,m) chains =================
__global__ __launch_bounds__(1024)
void k_compact(const int* __restrict__ numrec, int N)
{
    __shared__ int s_sum[1024];
    const int tid = threadIdx.x;
    const int per = (N + 1023) / 1024;
    int nr[8];
    int loc = 0;
    for (int i = 0; i < per; i++) {
        int n = tid * per + i;
        int v = 0;
        if (n < N) {
            v = numrec[(size_t)n * TT];
            if (v > MM) v = MM;
            if (v < 0)  v = 0;
        }
        nr[i] = v;
        loc += v;
    }
    s_sum[tid] = loc;
    __syncthreads();
    for (int off = 1; off < 1024; off <<= 1) {
        int v = (tid >= off) ? s_sum[tid - off] : 0;
        __syncthreads();
        s_sum[tid] += v;
        __syncthreads();
    }
    int myoff = s_sum[tid] - loc;
    for (int i = 0; i < per; i++) {
        int n = tid * per + i;
        for (int m = 0; m < nr[i]; m++)
            d_list[myoff++] = n * MM + m;
    }
    if (tid == 1023) d_nvalid = s_sum[1023];
}

// ================= K1: GRU + p0, lane=(node,d), register weights, shuffle gather =================
// Warp = 3 nodes x 9 dims (lanes 27-31 duplicate). Block = 6 warps = 3 (n,t) graphs.
// Loop LDS: 1 STS + 6 LDS.32 per thread per round (message exchange only).
__global__ __launch_bounds__(192, 2)
void k1_gru(const float* __restrict__ nf, const float* __restrict__ pos,
            const float* __restrict__ attm,
            const float* __restrict__ msgW, const float* __restrict__ msgb,
            const float* __restrict__ gWih, const float* __restrict__ gWhh,
            const float* __restrict__ gbih, const float* __restrict__ gbhh,
            const float* __restrict__ ro1W, const float* __restrict__ ro1b,
            const float* __restrict__ ro2W, const float* __restrict__ ro2b,
            const int* __restrict__ numrec, float* __restrict__ out_p0, int N)
{
    __shared__ __align__(16) u64 s_Wp[3][9][10];   // [gate r/z/n][d][k] = (Wih, Whh) pair
    __shared__ __align__(16) u64 s_bp[3][12];      // (bih, bhh) per gate,d
    __shared__ __align__(16) float s_msgWr[9][12];
    __shared__ __align__(16) float s_msgb[12];
    __shared__ __align__(16) float s_ro1W[9][12], s_ro1b[12];
    __shared__ __align__(16) float s_ro2W[7][12], s_ro2b[8];
    __shared__ __align__(16) float s_msg[18*12];   // 18 nodes x stride 12

    const int tid = threadIdx.x;
    // ---- staging ----
    for (int i = tid; i < 243; i += 192) {
        int g = i / 81, r = i % 81, dd = r / 9, k = r % 9;
        int row = g*9 + dd;
        ((float2*)&s_Wp[g][dd][0])[k] = make_float2(gWih[row*9 + k], gWhh[row*9 + k]);
    }
    if (tid < 27) {
        int g = tid / 9, dd = tid % 9;
        s_bp[g][dd] = pk(gbih[g*9 + dd], gbhh[g*9 + dd]);
    }
    for (int i = tid; i < 81; i += 192) s_msgWr[i/9][i%9] = msgW[i];
    if (tid < 9) s_msgb[tid] = msgb[tid];
    for (int i = tid; i < 81; i += 192) s_ro1W[i/9][i%9] = ro1W[i];
    if (tid < 9) s_ro1b[tid] = ro1b[tid];
    for (int i = tid; i < 63; i += 192) s_ro2W[i/9][i%9] = ro2W[i];
    if (tid < 7) s_ro2b[tid] = ro2b[tid];
    __syncthreads();

    const int w = tid >> 5, lane = tid & 31;
    int c = lane / 9;
    const int d = lane % 9;
    const bool act = (c < 3);
    if (!act) c = 2;                     // lanes 27-31 duplicate (c=2,d)
    const int p  = w*3 + c;              // node index in block pool [0,18)
    const int gl = p / 6;                // in-block graph 0..2
    const int m  = p - gl*6;
    const int sl = c * 9;                // shuffle source base

    const int ntot = N * TT;
    int nt = blockIdx.x * 3 + gl;
    const bool vnt = (nt < ntot) && act;
    if (nt >= ntot) nt = 0;
    const int n = nt / TT, t = nt % TT;
    const int nr0 = numrec[(size_t)n * TT];
    const float vm = (m < nr0) ? 1.0f : 0.0f;

    // ---- per-lane register weights ----
    u64 wr[9], wz[9], wn[9];
    #pragma unroll
    for (int k = 0; k < 9; k++) {
        wr[k] = s_Wp[0][d][k];
        wz[k] = s_Wp[1][d][k];
        wn[k] = s_Wp[2][d][k];
    }
    const u64 br = s_bp[0][d], bz = s_bp[1][d], bn = s_bp[2][d];
    float mwr[9], r1w[9], r2w[9];
    #pragma unroll
    for (int k = 0; k < 9; k++) mwr[k] = s_msgWr[d][k];
    const float mb = s_msgb[d];
    #pragma unroll
    for (int k = 0; k < 9; k++) r1w[k] = s_ro1W[d][k];
    const float r1b = s_ro1b[d];
    const int d7 = (d < 7) ? d : 0;
    #pragma unroll
    for (int k = 0; k < 9; k++) r2w[k] = s_ro2W[d7][k];
    const float r2b = s_ro2b[d7];

    // ---- inputs ----
    float h = (d < 3) ? nf[(size_t)nt*18 + m*3 + d]
                      : pos[(size_t)nt*36 + m*6 + (d-3)];
    float attr[6];
    #pragma unroll
    for (int j = 0; j < 6; j++)
        attr[j] = (j < nr0) ? attm[(size_t)nt*36 + m*6 + j] : 0.0f;

    // ---- 2 rounds of message passing ----
    #pragma unroll
    for (int rd = 0; rd < 2; rd++) {
        float hf[9];
        #pragma unroll
        for (int k = 0; k < 9; k++) hf[k] = __shfl_sync(0xffffffffu, h, sl + k);
        float msg = mb;
        #pragma unroll
        for (int k = 0; k < 9; k++) msg = fmaf(mwr[k], hf[k], msg);
        if (act) s_msg[p*12 + d] = msg;
        __syncthreads();
        float mg = 0.0f;
        const float* mrow = s_msg + (p - m)*12 + d;
        #pragma unroll
        for (int j = 0; j < 6; j++) mg = fmaf(attr[j], mrow[j*12], mg);
        __syncthreads();
        float mgf[9];
        #pragma unroll
        for (int k = 0; k < 9; k++) mgf[k] = __shfl_sync(0xffffffffu, mg, sl + k);
        u64 v[9];
        #pragma unroll
        for (int k = 0; k < 9; k++) v[k] = pk(mgf[k], hf[k]);
        u64 ar = br, az = bz, an = bn;
        #pragma unroll
        for (int k = 0; k < 9; k++) {
            ar = ffma2(wr[k], v[k], ar);
            az = ffma2(wz[k], v[k], az);
            an = ffma2(wn[k], v[k], an);
        }
        float e, o;
        upk(e, o, ar); float r_ = fsig_fast(e + o);
        upk(e, o, az); float z_ = fsig_fast(e + o);
        float gx2, gh2; upk(gx2, gh2, an);
        float nn = ftanh_fast(fmaf(r_, gh2, gx2));
        h = fmaf(z_, h - nn, nn) * vm;
    }

    // ---- store hidden for LSTM ----
    if (vnt) g_hidden[((size_t)t * (N*MM) + (size_t)n*MM + m) * 12 + d] = h;

    // ---- p0 readout ----
    float hf[9];
    #pragma unroll
    for (int k = 0; k < 9; k++) hf[k] = __shfl_sync(0xffffffffu, h, sl + k);
    float q = r1b;
    #pragma unroll
    for (int k = 0; k < 9; k++) q = fmaf(r1w[k], hf[k], q);
    q = fmaxf(q, 0.0f);
    float qf[9];
    #pragma unroll
    for (int k = 0; k < 9; k++) qf[k] = __shfl_sync(0xffffffffu, q, sl + k);
    if (vnt && d < 7) {
        float ov = r2b;
        #pragma unroll
        for (int k = 0; k < 9; k++) ov = fmaf(r2w[k], qf[k], ov);
        out_p0[((size_t)n*(TT*MM) + t*MM + m) * 7 + d] = ov * vm;
    }
}

// ================= K2: Bi-LSTM, 2 chains/lane, register weights, MUFU.TANH =================
__global__ __launch_bounds__(128, 3)
void k2_lstm(const float* __restrict__ lfWih, const float* __restrict__ lfWhh,
             const float* __restrict__ lfbih, const float* __restrict__ lfbhh,
             const float* __restrict__ lbWih, const float* __restrict__ lbWhh,
             const float* __restrict__ lbbih, const float* __restrict__ lbbhh,
             int N)
{
    __shared__ __align__(16) u64 s_W[2][9][4][10];   // [dir][d][gate][k-pair]
    __shared__ __align__(16) u64 s_b[2][9][4];       // (bih+bhh, 0)

    const int tid = threadIdx.x;
    for (int i = tid; i < 648; i += 128) {
        int dirn = i / 324, r = i % 324;
        int d = r / 36, rr = r % 36, gi = rr / 9, e = rr % 9;
        const float* Wi = dirn ? lbWih : lfWih;
        const float* Wh = dirn ? lbWhh : lfWhh;
        int row = gi*9 + d;
        int j0 = 2*e, j1 = 2*e + 1;
        float lo = (j0 < 9) ? Wi[row*9 + j0] : Wh[row*9 + (j0-9)];
        float hi = (j1 < 9) ? Wi[row*9 + j1] : Wh[row*9 + (j1-9)];
        ((float2*)&s_W[dirn][d][gi][0])[e] = make_float2(lo, hi);
    }
    for (int i = tid; i < 72; i += 128) {
        int dirn = i / 36, r = i % 36, d = r / 4, gi = r % 4;
        const float* bi = dirn ? lbbih : lfbih;
        const float* bh = dirn ? lbbhh : lfbhh;
        s_b[dirn][d][gi] = pk(bi[gi*9+d] + bh[gi*9+d], 0.0f);
    }
    __syncthreads();

    const int half   = N * MM;
    const int nvalid = d_nvalid;
    const int Wdw    = (half + 5) / 6;
    const int wglob  = blockIdx.x * 4 + (tid >> 5);
    if (wglob >= 2 * Wdw) return;
    const int dirn = (wglob >= Wdw) ? 1 : 0;
    const int base = (wglob - dirn * Wdw) * 6;
    if (base >= nvalid) return;

    const int lane = tid & 31;
    int c = lane / 9;
    const int d = lane % 9;
    bool act = (c < 3);
    if (!act) c = 2;
    const int slane = c * 9;

    int liA = base + 2*c, liB = liA + 1;
    bool actA = act && (liA < nvalid);
    bool actB = act && (liB < nvalid);
    if (liA >= nvalid) liA = nvalid - 1;
    if (liB >= nvalid) liB = nvalid - 1;
    const int nmA = d_list[liA];
    const int nmB = d_list[liB];

    u64 w0[9], w1[9], w2[9], w3[9];
    #pragma unroll
    for (int k = 0; k < 9; k++) {
        w0[k] = s_W[dirn][d][0][k];
        w1[k] = s_W[dirn][d][1][k];
        w2[k] = s_W[dirn][d][2][k];
        w3[k] = s_W[dirn][d][3][k];
    }
    const u64 bb0 = s_b[dirn][d][0], bb1 = s_b[dirn][d][1];
    const u64 bb2 = s_b[dirn][d][2], bb3 = s_b[dirn][d][3];

    const long tstep = (long)half * 12;
    const long sstep = dirn ? -tstep : tstep;
    const size_t t0  = dirn ? (size_t)(TT-1)*tstep : 0;
    const float* xpA = g_hidden + (size_t)nmA*12 + t0;
    const float* xpB = g_hidden + (size_t)nmB*12 + t0;
    float* opA = g_lstm[dirn] + (size_t)nmA*12 + t0;
    float* opB = g_lstm[dirn] + (size_t)nmB*12 + t0;

    float hdA = 0.0f, cdA = 0.0f, hdB = 0.0f, cdB = 0.0f;

    for (int s = 0; s < TT; s++) {
        ulonglong2 xaA = *(const ulonglong2*)xpA;
        ulonglong2 xbA = *(const ulonglong2*)(xpA + 4);
        float x8A = xpA[8];
        ulonglong2 xaB = *(const ulonglong2*)xpB;
        ulonglong2 xbB = *(const ulonglong2*)(xpB + 4);
        float x8B = xpB[8];

        float hA0 = __shfl_sync(0xffffffffu, hdA, slane + 0);
        float hA1 = __shfl_sync(0xffffffffu, hdA, slane + 1);
        float hA2 = __shfl_sync(0xffffffffu, hdA, slane + 2);
        float hA3 = __shfl_sync(0xffffffffu, hdA, slane + 3);
        float hA4 = __shfl_sync(0xffffffffu, hdA, slane + 4);
        float hA5 = __shfl_sync(0xffffffffu, hdA, slane + 5);
        float hA6 = __shfl_sync(0xffffffffu, hdA, slane + 6);
        float hA7 = __shfl_sync(0xffffffffu, hdA, slane + 7);
        float hA8 = __shfl_sync(0xffffffffu, hdA, slane + 8);
        float hB0 = __shfl_sync(0xffffffffu, hdB, slane + 0);
        float hB1 = __shfl_sync(0xffffffffu, hdB, slane + 1);
        float hB2 = __shfl_sync(0xffffffffu, hdB, slane + 2);
        float hB3 = __shfl_sync(0xffffffffu, hdB, slane + 3);
        float hB4 = __shfl_sync(0xffffffffu, hdB, slane + 4);
        float hB5 = __shfl_sync(0xffffffffu, hdB, slane + 5);
        float hB6 = __shfl_sync(0xffffffffu, hdB, slane + 6);
        float hB7 = __shfl_sync(0xffffffffu, hdB, slane + 7);
        float hB8 = __shfl_sync(0xffffffffu, hdB, slane + 8);

        u64 vA[9], vB[9];
        vA[0] = xaA.x; vA[1] = xaA.y; vA[2] = xbA.x; vA[3] = xbA.y;
        vA[4] = pk(x8A, hA0); vA[5] = pk(hA1, hA2); vA[6] = pk(hA3, hA4);
        vA[7] = pk(hA5, hA6); vA[8] = pk(hA7, hA8);
        vB[0] = xaB.x; vB[1] = xaB.y; vB[2] = xbB.x; vB[3] = xbB.y;
        vB[4] = pk(x8B, hB0); vB[5] = pk(hB1, hB2); vB[6] = pk(hB3, hB4);
        vB[7] = pk(hB5, hB6); vB[8] = pk(hB7, hB8);

        u64 aA0 = bb0, aA1 = bb1, aA2 = bb2, aA3 = bb3;
        u64 aB0 = bb0, aB1 = bb1, aB2 = bb2, aB3 = bb3;
        #pragma unroll
        for (int k = 0; k < 9; k++) {
            aA0 = ffma2(w0[k], vA[k], aA0);
            aB0 = ffma2(w0[k], vB[k], aB0);
            aA1 = ffma2(w1[k], vA[k], aA1);
            aB1 = ffma2(w1[k], vB[k], aB1);
            aA2 = ffma2(w2[k], vA[k], aA2);
            aB2 = ffma2(w2[k], vB[k], aB2);
            aA3 = ffma2(w3[k], vA[k], aA3);
            aB3 = ffma2(w3[k], vB[k], aB3);
        }
        float e0,o0,e1,o1,e2,o2,e3,o3;
        upk(e0,o0,aA0); upk(e1,o1,aA1); upk(e2,o2,aA2); upk(e3,o3,aA3);
        {
            float i_ = fsig_fast(e0 + o0);
            float f_ = fsig_fast(e1 + o1);
            float gg = ftanh_fast(e2 + o2);
            float o_ = fsig_fast(e3 + o3);
            cdA = fmaf(f_, cdA, i_ * gg);
            hdA = o_ * ftanh_fast(cdA);
        }
        upk(e0,o0,aB0); upk(e1,o1,aB1); upk(e2,o2,aB2); upk(e3,o3,aB3);
        {
            float i_ = fsig_fast(e0 + o0);
            float f_ = fsig_fast(e1 + o1);
            float gg = ftanh_fast(e2 + o2);
            float o_ = fsig_fast(e3 + o3);
            cdB = fmaf(f_, cdB, i_ * gg);
            hdB = o_ * ftanh_fast(cdB);
        }

        if (actA) opA[d] = hdA;
        if (actB) opB[d] = hdB;
        xpA += sstep; xpB += sstep; opA += sstep; opB += sstep;
    }
}

// ================= K3: final readout p — early-zero for invalid nodes =================
__global__ __launch_bounds__(256)
void k3_readout(const float* __restrict__ lr1W, const float* __restrict__ lr1b,
                const float* __restrict__ lr2W, const float* __restrict__ lr2b,
                const int* __restrict__ numrec, float* __restrict__ out_p, int N)
{
    __shared__ __align__(16) u64 s_R1[4][20];
    __shared__ __align__(16) u64 s_R1b[4];
    __shared__ __align__(16) u64 s_R2[3][10];
    __shared__ __align__(16) u64 s_R2b[3];
    __shared__ __align__(16) float s_R1s[20], s_R2s[12];
    __shared__ float s_R1bs, s_R2bs;

    const int tid = threadIdx.x;
    for (int i = tid; i < 72; i += 256) {
        int p = i/18, k = i%18;
        ((float2*)&s_R1[p][0])[k] = make_float2(lr1W[(2*p)*18+k], lr1W[(2*p+1)*18+k]);
    }
    if (tid < 18) s_R1s[tid] = lr1W[8*18 + tid];
    for (int i = tid; i < 27; i += 256) {
        int p = i/9, k = i%9;
        ((float2*)&s_R2[p][0])[k] = make_float2(lr2W[(2*p)*9+k], lr2W[(2*p+1)*9+k]);
    }
    if (tid < 9) s_R2s[tid] = lr2W[6*9 + tid];
    if (tid < 4) ((float2*)s_R1b)[tid] = make_float2(lr1b[2*tid], lr1b[2*tid+1]);
    if (tid == 4) s_R1bs = lr1b[8];
    if (tid < 3) ((float2*)s_R2b)[tid] = make_float2(lr2b[2*tid], lr2b[2*tid+1]);
    if (tid == 3) s_R2bs = lr2b[6];
    __syncthreads();

    const int half = N * MM;
    const int id = blockIdx.x * 256 + tid;
    if (id >= TT * half) return;
    const int t = id / half;
    const int nm = id - t * half;
    const int n = nm / MM, m = nm - n*MM;
    const int nr0 = numrec[(size_t)n * TT];
    float* po = out_p + ((size_t)n*(TT*MM) + t*MM + m) * 7;

    if (m >= nr0) {
        #pragma unroll
        for (int k = 0; k < 7; k++) po[k] = 0.0f;
        return;
    }

    float o18[18];
    load9(o18,     g_lstm[0] + ((size_t)t*half + nm)*12);
    load9(o18 + 9, g_lstm[1] + ((size_t)t*half + nm)*12);
    u64 o2[18];
    #pragma unroll
    for (int k = 0; k < 18; k++) o2[k] = pk(o18[k], o18[k]);

    float q[9];
    #pragma unroll
    for (int p = 0; p < 4; p++) {
        u64 acc = s_R1b[p];
        #pragma unroll
        for (int k = 0; k < 18; k++) acc = ffma2(s_R1[p][k], o2[k], acc);
        float a, b; upk(a, b, acc);
        q[2*p]   = fmaxf(a, 0.0f);
        q[2*p+1] = fmaxf(b, 0.0f);
    }
    {
        float acc = s_R1bs;
        #pragma unroll
        for (int k = 0; k < 18; k++) acc = fmaf(s_R1s[k], o18[k], acc);
        q[8] = fmaxf(acc, 0.0f);
    }
    u64 q2[9];
    #pragma unroll
    for (int k = 0; k < 9; k++) q2[k] = pk(q[k], q[k]);

    float o7[7];
    #pragma unroll
    for (int p = 0; p < 3; p++) {
        u64 acc = s_R2b[p];
        #pragma unroll
        for (int k = 0; k < 9; k++) acc = ffma2(s_R2[p][k], q2[k], acc);
        upk(o7[2*p], o7[2*p+1], acc);
    }
    {
        float acc = s_R2bs;
        #pragma unroll
        for (int k = 0; k < 9; k++) acc = fmaf(s_R2s[k], q[k], acc);
        o7[6] = acc;
    }

    #pragma unroll
    for (int k = 0; k < 7; k++) po[k] = o7[k];
}

extern "C" void kernel_launch(void* const* d_in, const int* in_sizes, int n_in,
                              void* d_out, int out_size)
{
    const float* nf    = (const float*)d_in[0];
    const float* pos   = (const float*)d_in[1];
    const float* attm  = (const float*)d_in[2];
    const float* msgW  = (const float*)d_in[3];
    const float* msgb  = (const float*)d_in[4];
    const float* gWih  = (const float*)d_in[5];
    const float* gWhh  = (const float*)d_in[6];
    const float* gbih  = (const float*)d_in[7];
    const float* gbhh  = (const float*)d_in[8];
    const float* ro1W  = (const float*)d_in[9];
    const float* ro1b  = (const float*)d_in[10];
    const float* ro2W  = (const float*)d_in[11];
    const float* ro2b  = (const float*)d_in[12];
    const float* lfWih = (const float*)d_in[13];
    const float* lfWhh = (const float*)d_in[14];
    const float* lfbih = (const float*)d_in[15];
    const float* lfbhh = (const float*)d_in[16];
    const float* lbWih = (const float*)d_in[17];
    const float* lbWhh = (const float*)d_in[18];
    const float* lbbih = (const float*)d_in[19];
    const float* lbbhh = (const float*)d_in[20];
    const float* lr1W  = (const float*)d_in[21];
    const float* lr1b  = (const float*)d_in[22];
    const float* lr2W  = (const float*)d_in[23];
    const float* lr2b  = (const float*)d_in[24];
    const int*   nrec  = (const int*)d_in[25];

    const int N = in_sizes[25] / TT;
    float* out = (float*)d_out;
    float* out_p  = out;                              // pred_label
    float* out_p0 = out + (size_t)N * TT * MM * 7;    // pred_label0

    const int grid1 = (N*TT + 2) / 3;                 // 3 graphs per block
    const int Wdw   = (N*MM + 5) / 6;
    const int grid2 = (2*Wdw + 3) / 4;
    const int grid3 = (N*TT*MM + 255) / 256;

    k_compact<<<1, 1024>>>(nrec, N);                   // launch #1
    k1_gru<<<grid1, 192>>>(nf, pos, attm, msgW, msgb, gWih, gWhh, gbih, gbhh,
                           ro1W, ro1b, ro2W, ro2b, nrec, out_p0, N);   // #2
    k2_lstm<<<grid2, 128>>>(lfWih, lfWhh, lfbih, lfbhh,
                            lbWih, lbWhh, lbbih, lbbhh, N);            // #3
    k3_readout<<<grid3, 256>>>(lr1W, lr1b, lr2W, lr2b, nrec, out_p, N); // #4 (profiled)
}

// round 16
// speedup vs baseline: 2.3718x; 2.3718x over previous
#include <cuda_runtime.h>

#define TT 20
#define MM 6
#define MAXN 8192
typedef unsigned long long u64;

// scratch (allocation-free rule: __device__ globals)
__device__ __align__(16) float g_hidden[(size_t)TT * MAXN * MM * 12];
__device__ __align__(16) float g_lstm[2][(size_t)TT * MAXN * MM * 12];
__device__ int d_list[MAXN * MM];
__device__ int d_nvalid;

// ---------------- f32x2 helpers ----------------
__device__ __forceinline__ u64 pk(float a, float b) {
    u64 r; asm("mov.b64 %0, {%1, %2};" : "=l"(r) : "f"(a), "f"(b)); return r;
}
__device__ __forceinline__ void upk(float& a, float& b, u64 v) {
    asm("mov.b64 {%0, %1}, %2;" : "=f"(a), "=f"(b) : "l"(v));
}
__device__ __forceinline__ u64 ffma2(u64 a, u64 b, u64 c) {
    u64 r; asm("fma.rn.f32x2 %0, %1, %2, %3;" : "=l"(r) : "l"(a), "l"(b), "l"(c)); return r;
}

// packed 9-dot: W[0..8] (pairs), v[0..8] (pairs)
__device__ __forceinline__ u64 dotp9(const u64* __restrict__ W, const u64* v, u64 acc) {
    #pragma unroll
    for (int kk = 0; kk < 4; kk++) {
        ulonglong2 w = *(const ulonglong2*)(W + 2*kk);
        acc = ffma2(w.x, v[2*kk],   acc);
        acc = ffma2(w.y, v[2*kk+1], acc);
    }
    acc = ffma2(W[8], v[8], acc);
    return acc;
}
// packed 18-dot: W[0..8] vs va, W[10..18] vs vb
__device__ __forceinline__ u64 dotp18(const u64* __restrict__ W, const u64* va, const u64* vb, u64 acc) {
    acc = dotp9(W, va, acc);
    acc = dotp9(W + 10, vb, acc);
    return acc;
}

// ---------------- MUFU.TANH activations (proven: rel_err ~1.5e-6 end-to-end) ----------------
__device__ __forceinline__ float ftanh_fast(float x) {
    float t; asm("tanh.approx.f32 %0, %1;" : "=f"(t) : "f"(x));
    return t;
}
__device__ __forceinline__ float fsig_fast(float x) {
    float t; asm("tanh.approx.f32 %0, %1;" : "=f"(t) : "f"(0.5f * x));
    return fmaf(0.5f, t, 0.5f);
}

// ---------------- scalar dot helpers ----------------
__device__ __forceinline__ float dot9(const float* __restrict__ w, const float* r) {
    float4 a = *(const float4*)w;
    float4 b = *(const float4*)(w + 4);
    float acc = w[8] * r[8];
    acc = fmaf(a.x, r[0], acc); acc = fmaf(a.y, r[1], acc);
    acc = fmaf(a.z, r[2], acc); acc = fmaf(a.w, r[3], acc);
    acc = fmaf(b.x, r[4], acc); acc = fmaf(b.y, r[5], acc);
    acc = fmaf(b.z, r[6], acc); acc = fmaf(b.w, r[7], acc);
    return acc;
}
__device__ __forceinline__ void load9(float* r, const float* __restrict__ p) {
    float4 a = *(const float4*)p;
    float4 b = *(const float4*)(p + 4);
    r[0]=a.x; r[1]=a.y; r[2]=a.z; r[3]=a.w;
    r[4]=b.x; r[5]=b.y; r[6]=b.z; r[7]=b.w;
    r[8]=p[8];
}
__device__ __forceinline__ void store9(float* __restrict__ p, const float* r) {
    *(float4*)p       = make_float4(r[0], r[1], r[2], r[3]);
    *(float4*)(p + 4) = make_float4(r[4], r[5], r[6], r[7]);
    p[8] = r[8];
}

// ================= KC: deterministic compaction of valid (n,m) chains =================
__global__ __launch_bounds__(1024)
void k_compact(const int* __restrict__ numrec, int N)
{
    __shared__ int s_sum[1024];
    const int tid = threadIdx.x;
    const int per = (N + 1023) / 1024;
    int nr[8];
    int loc = 0;
    for (int i = 0; i < per; i++) {
        int n = tid * per + i;
        int v = 0;
        if (n < N) {
            v = numrec[(size_t)n * TT];
            if (v > MM) v = MM;
            if (v < 0)  v = 0;
        }
        nr[i] = v;
        loc += v;
    }
    s_sum[tid] = loc;
    __syncthreads();
    for (int off = 1; off < 1024; off <<= 1) {
        int v = (tid >= off) ? s_sum[tid - off] : 0;
        __syncthreads();
        s_sum[tid] += v;
        __syncthreads();
    }
    int myoff = s_sum[tid] - loc;
    for (int i = 0; i < per; i++) {
        int n = tid * per + i;
        for (int m = 0; m < nr[i]; m++)
            d_list[myoff++] = n * MM + m;
    }
    if (tid == 1023) d_nvalid = s_sum[1023];
}

// ================= K1: GRU message passing + p0 readout (MUFU.TANH activations) =================
__global__ __launch_bounds__(192)
void k1_gru(const float* __restrict__ nf, const float* __restrict__ pos,
            const float* __restrict__ attm,
            const float* __restrict__ msgW, const float* __restrict__ msgb,
            const float* __restrict__ gWih, const float* __restrict__ gWhh,
            const float* __restrict__ gbih, const float* __restrict__ gbhh,
            const float* __restrict__ ro1W, const float* __restrict__ ro1b,
            const float* __restrict__ ro2W, const float* __restrict__ ro2b,
            const int* __restrict__ numrec, float* __restrict__ out_p0, int N)
{
    __shared__ __align__(16) u64 s_PM[4][10];
    __shared__ __align__(16) u64 s_P1[9][20];
    __shared__ __align__(16) u64 s_P3[9][10];
    __shared__ __align__(16) u64 s_bA[9], s_b3[9], s_bm[4];
    __shared__ __align__(16) float s_msgW8[12], s_ro1W[9*12], s_ro2W[7*12];
    __shared__ __align__(16) float s_ro1b[12], s_ro2b[8];
    __shared__ float s_bm8;
    __shared__ __align__(16) float s_msg[192*12];

    const int tid = threadIdx.x;
    for (int i = tid; i < 36; i += 192) {
        int p = i/9, k = i%9;
        ((float2*)s_PM)[p*10 + k] = make_float2(msgW[(2*p)*9 + k], msgW[(2*p+1)*9 + k]);
    }
    for (int i = tid; i < 162; i += 192) {
        int d = i/18, k = i%18;
        float lo, hi; int idx;
        if (k < 9) { lo = gWih[d*9+k];        hi = gWih[(9+d)*9+k];        idx = d*20 + k; }
        else { int kk = k-9; lo = gWhh[d*9+kk]; hi = gWhh[(9+d)*9+kk];     idx = d*20 + 10 + kk; }
        ((float2*)s_P1)[idx] = make_float2(lo, hi);
    }
    for (int i = tid; i < 81; i += 192) {
        int d = i/9, k = i%9;
        ((float2*)s_P3)[d*10 + k] = make_float2(gWih[(18+d)*9+k], gWhh[(18+d)*9+k]);
    }
    if (tid < 4) ((float2*)s_bm)[tid] = make_float2(msgb[2*tid], msgb[2*tid+1]);
    if (tid == 4) s_bm8 = msgb[8];
    if (tid < 9) {
        ((float2*)s_bA)[tid] = make_float2(gbih[tid] + gbhh[tid], gbih[9+tid] + gbhh[9+tid]);
        ((float2*)s_b3)[tid] = make_float2(gbih[18+tid], gbhh[18+tid]);
        s_msgW8[tid] = msgW[8*9 + tid];
        s_ro1b[tid] = ro1b[tid];
    }
    for (int i = tid; i < 81; i += 192) s_ro1W[(i/9)*12 + i%9] = ro1W[i];
    for (int i = tid; i < 63; i += 192) s_ro2W[(i/9)*12 + i%9] = ro2W[i];
    if (tid < 7) s_ro2b[tid] = ro2b[tid];

    const int g = tid / 6, m = tid % 6;
    const int ntot = N * TT;
    int nt = blockIdx.x * 32 + g;
    const bool vnt = nt < ntot;
    if (!vnt) nt = 0;
    const int n = nt / TT, t = nt % TT;
    const int nr0 = numrec[(size_t)n * TT];
    const float vm = (m < nr0) ? 1.0f : 0.0f;

    float h[9], attr[6];
    {
        const float* q = nf + (size_t)nt*18 + m*3;
        h[0]=q[0]; h[1]=q[1]; h[2]=q[2];
        const float* pq = pos + (size_t)nt*36 + m*6;
        #pragma unroll
        for (int j = 0; j < 6; j++) h[3+j] = pq[j];
        const float* aq = attm + (size_t)nt*36 + m*6;
        #pragma unroll
        for (int j = 0; j < 6; j++) attr[j] = (j < nr0) ? aq[j] : 0.0f;
    }
    u64 a2[6];
    #pragma unroll
    for (int j = 0; j < 6; j++) a2[j] = pk(attr[j], attr[j]);
    __syncthreads();

    #pragma unroll
    for (int rd = 0; rd < 2; rd++) {
        u64 hd2[9];
        #pragma unroll
        for (int k = 0; k < 9; k++) hd2[k] = pk(h[k], h[k]);
        float msg[9];
        #pragma unroll
        for (int p = 0; p < 4; p++) {
            u64 acc = dotp9(&s_PM[p][0], hd2, s_bm[p]);
            upk(msg[2*p], msg[2*p+1], acc);
        }
        msg[8] = s_bm8 + dot9(s_msgW8, h);
        store9(s_msg + tid*12, msg);
        __syncthreads();
        u64 mgp[4] = {0,0,0,0};
        float mg8 = 0.0f;
        #pragma unroll
        for (int j = 0; j < 6; j++) {
            const float* mp = s_msg + (g*6 + j)*12;
            const u64* mpp = (const u64*)mp;
            mgp[0] = ffma2(a2[j], mpp[0], mgp[0]);
            mgp[1] = ffma2(a2[j], mpp[1], mgp[1]);
            mgp[2] = ffma2(a2[j], mpp[2], mgp[2]);
            mgp[3] = ffma2(a2[j], mpp[3], mgp[3]);
            mg8 = fmaf(attr[j], mp[8], mg8);
        }
        float mg[9];
        #pragma unroll
        for (int p = 0; p < 4; p++) upk(mg[2*p], mg[2*p+1], mgp[p]);
        mg[8] = mg8;
        u64 mg2[9], mh2[9];
        #pragma unroll
        for (int k = 0; k < 9; k++) { mg2[k] = pk(mg[k], mg[k]); mh2[k] = pk(mg[k], h[k]); }
        float hn[9];
        #pragma unroll
        for (int d = 0; d < 9; d++) {
            u64 acc1 = dotp18(&s_P1[d][0], mg2, hd2, s_bA[d]);
            u64 acc3 = dotp9(&s_P3[d][0], mh2, s_b3[d]);
            float a0, a1, gx2, gh2;
            upk(a0, a1, acc1);
            upk(gx2, gh2, acc3);
            float r  = fsig_fast(a0);
            float z  = fsig_fast(a1);
            float nn = ftanh_fast(fmaf(r, gh2, gx2));
            hn[d] = fmaf(z, h[d] - nn, nn) * vm;
        }
        #pragma unroll
        for (int d = 0; d < 9; d++) h[d] = hn[d];
        __syncthreads();
    }

    if (vnt) {
        store9(g_hidden + ((size_t)t * (N*MM) + n*MM + m) * 12, h);
        float q[9];
        #pragma unroll
        for (int d = 0; d < 9; d++)
            q[d] = fmaxf(s_ro1b[d] + dot9(s_ro1W + d*12, h), 0.0f);
        float* po = out_p0 + ((size_t)n*(TT*MM) + t*MM + m) * 7;
        #pragma unroll
        for (int k = 0; k < 7; k++)
            po[k] = (s_ro2b[k] + dot9(s_ro2W + k*12, q)) * vm;
    }
}

// ================= K2: Bi-LSTM, 2 chains/lane, register weights, MUFU.TANH =================
__global__ __launch_bounds__(128, 3)
void k2_lstm(const float* __restrict__ lfWih, const float* __restrict__ lfWhh,
             const float* __restrict__ lfbih, const float* __restrict__ lfbhh,
             const float* __restrict__ lbWih, const float* __restrict__ lbWhh,
             const float* __restrict__ lbbih, const float* __restrict__ lbbhh,
             int N)
{
    __shared__ __align__(16) u64 s_W[2][9][4][10];   // [dir][d][gate][k-pair]
    __shared__ __align__(16) u64 s_b[2][9][4];       // (bih+bhh, 0)

    const int tid = threadIdx.x;
    for (int i = tid; i < 648; i += 128) {
        int dirn = i / 324, r = i % 324;
        int d = r / 36, rr = r % 36, gi = rr / 9, e = rr % 9;
        const float* Wi = dirn ? lbWih : lfWih;
        const float* Wh = dirn ? lbWhh : lfWhh;
        int row = gi*9 + d;
        int j0 = 2*e, j1 = 2*e + 1;
        float lo = (j0 < 9) ? Wi[row*9 + j0] : Wh[row*9 + (j0-9)];
        float hi = (j1 < 9) ? Wi[row*9 + j1] : Wh[row*9 + (j1-9)];
        ((float2*)&s_W[dirn][d][gi][0])[e] = make_float2(lo, hi);
    }
    for (int i = tid; i < 72; i += 128) {
        int dirn = i / 36, r = i % 36, d = r / 4, gi = r % 4;
        const float* bi = dirn ? lbbih : lfbih;
        const float* bh = dirn ? lbbhh : lfbhh;
        s_b[dirn][d][gi] = pk(bi[gi*9+d] + bh[gi*9+d], 0.0f);
    }
    __syncthreads();

    const int half   = N * MM;
    const int nvalid = d_nvalid;
    const int Wdw    = (half + 5) / 6;
    const int wglob  = blockIdx.x * 4 + (tid >> 5);
    if (wglob >= 2 * Wdw) return;
    const int dirn = (wglob >= Wdw) ? 1 : 0;
    const int base = (wglob - dirn * Wdw) * 6;
    if (base >= nvalid) return;

    const int lane = tid & 31;
    int c = lane / 9;
    const int d = lane % 9;
    bool act = (c < 3);
    if (!act) c = 2;
    const int slane = c * 9;

    int liA = base + 2*c, liB = liA + 1;
    bool actA = act && (liA < nvalid);
    bool actB = act && (liB < nvalid);
    if (liA >= nvalid) liA = nvalid - 1;
    if (liB >= nvalid) liB = nvalid - 1;
    const int nmA = d_list[liA];
    const int nmB = d_list[liB];

    u64 w0[9], w1[9], w2[9], w3[9];
    #pragma unroll
    for (int k = 0; k < 9; k++) {
        w0[k] = s_W[dirn][d][0][k];
        w1[k] = s_W[dirn][d][1][k];
        w2[k] = s_W[dirn][d][2][k];
        w3[k] = s_W[dirn][d][3][k];
    }
    const u64 bb0 = s_b[dirn][d][0], bb1 = s_b[dirn][d][1];
    const u64 bb2 = s_b[dirn][d][2], bb3 = s_b[dirn][d][3];

    const long tstep = (long)half * 12;
    const long sstep = dirn ? -tstep : tstep;
    const size_t t0  = dirn ? (size_t)(TT-1)*tstep : 0;
    const float* xpA = g_hidden + (size_t)nmA*12 + t0;
    const float* xpB = g_hidden + (size_t)nmB*12 + t0;
    float* opA = g_lstm[dirn] + (size_t)nmA*12 + t0;
    float* opB = g_lstm[dirn] + (size_t)nmB*12 + t0;

    float hdA = 0.0f, cdA = 0.0f, hdB = 0.0f, cdB = 0.0f;

    for (int s = 0; s < TT; s++) {
        ulonglong2 xaA = *(const ulonglong2*)xpA;
        ulonglong2 xbA = *(const ulonglong2*)(xpA + 4);
        float x8A = xpA[8];
        ulonglong2 xaB = *(const ulonglong2*)xpB;
        ulonglong2 xbB = *(const ulonglong2*)(xpB + 4);
        float x8B = xpB[8];

        float hA0 = __shfl_sync(0xffffffffu, hdA, slane + 0);
        float hA1 = __shfl_sync(0xffffffffu, hdA, slane + 1);
        float hA2 = __shfl_sync(0xffffffffu, hdA, slane + 2);
        float hA3 = __shfl_sync(0xffffffffu, hdA, slane + 3);
        float hA4 = __shfl_sync(0xffffffffu, hdA, slane + 4);
        float hA5 = __shfl_sync(0xffffffffu, hdA, slane + 5);
        float hA6 = __shfl_sync(0xffffffffu, hdA, slane + 6);
        float hA7 = __shfl_sync(0xffffffffu, hdA, slane + 7);
        float hA8 = __shfl_sync(0xffffffffu, hdA, slane + 8);
        float hB0 = __shfl_sync(0xffffffffu, hdB, slane + 0);
        float hB1 = __shfl_sync(0xffffffffu, hdB, slane + 1);
        float hB2 = __shfl_sync(0xffffffffu, hdB, slane + 2);
        float hB3 = __shfl_sync(0xffffffffu, hdB, slane + 3);
        float hB4 = __shfl_sync(0xffffffffu, hdB, slane + 4);
        float hB5 = __shfl_sync(0xffffffffu, hdB, slane + 5);
        float hB6 = __shfl_sync(0xffffffffu, hdB, slane + 6);
        float hB7 = __shfl_sync(0xffffffffu, hdB, slane + 7);
        float hB8 = __shfl_sync(0xffffffffu, hdB, slane + 8);

        u64 vA[9], vB[9];
        vA[0] = xaA.x; vA[1] = xaA.y; vA[2] = xbA.x; vA[3] = xbA.y;
        vA[4] = pk(x8A, hA0); vA[5] = pk(hA1, hA2); vA[6] = pk(hA3, hA4);
        vA[7] = pk(hA5, hA6); vA[8] = pk(hA7, hA8);
        vB[0] = xaB.x; vB[1] = xaB.y; vB[2] = xbB.x; vB[3] = xbB.y;
        vB[4] = pk(x8B, hB0); vB[5] = pk(hB1, hB2); vB[6] = pk(hB3, hB4);
        vB[7] = pk(hB5, hB6); vB[8] = pk(hB7, hB8);

        u64 aA0 = bb0, aA1 = bb1, aA2 = bb2, aA3 = bb3;
        u64 aB0 = bb0, aB1 = bb1, aB2 = bb2, aB3 = bb3;
        #pragma unroll
        for (int k = 0; k < 9; k++) {
            aA0 = ffma2(w0[k], vA[k], aA0);
            aB0 = ffma2(w0[k], vB[k], aB0);
            aA1 = ffma2(w1[k], vA[k], aA1);
            aB1 = ffma2(w1[k], vB[k], aB1);
            aA2 = ffma2(w2[k], vA[k], aA2);
            aB2 = ffma2(w2[k], vB[k], aB2);
            aA3 = ffma2(w3[k], vA[k], aA3);
            aB3 = ffma2(w3[k], vB[k], aB3);
        }
        float e0,o0,e1,o1,e2,o2,e3,o3;
        upk(e0,o0,aA0); upk(e1,o1,aA1); upk(e2,o2,aA2); upk(e3,o3,aA3);
        {
            float i_ = fsig_fast(e0 + o0);
            float f_ = fsig_fast(e1 + o1);
            float gg = ftanh_fast(e2 + o2);
            float o_ = fsig_fast(e3 + o3);
            cdA = fmaf(f_, cdA, i_ * gg);
            hdA = o_ * ftanh_fast(cdA);
        }
        upk(e0,o0,aB0); upk(e1,o1,aB1); upk(e2,o2,aB2); upk(e3,o3,aB3);
        {
            float i_ = fsig_fast(e0 + o0);
            float f_ = fsig_fast(e1 + o1);
            float gg = ftanh_fast(e2 + o2);
            float o_ = fsig_fast(e3 + o3);
            cdB = fmaf(f_, cdB, i_ * gg);
            hdB = o_ * ftanh_fast(cdB);
        }

        if (actA) opA[d] = hdA;
        if (actB) opB[d] = hdB;
        xpA += sstep; xpB += sstep; opA += sstep; opB += sstep;
    }
}

// ================= K3: final readout p — early-zero for invalid nodes =================
__global__ __launch_bounds__(256)
void k3_readout(const float* __restrict__ lr1W, const float* __restrict__ lr1b,
                const float* __restrict__ lr2W, const float* __restrict__ lr2b,
                const int* __restrict__ numrec, float* __restrict__ out_p, int N)
{
    __shared__ __align__(16) u64 s_R1[4][20];
    __shared__ __align__(16) u64 s_R1b[4];
    __shared__ __align__(16) u64 s_R2[3][10];
    __shared__ __align__(16) u64 s_R2b[3];
    __shared__ __align__(16) float s_R1s[20], s_R2s[12];
    __shared__ float s_R1bs, s_R2bs;

    const int tid = threadIdx.x;
    for (int i = tid; i < 72; i += 256) {
        int p = i/18, k = i%18;
        ((float2*)&s_R1[p][0])[k] = make_float2(lr1W[(2*p)*18+k], lr1W[(2*p+1)*18+k]);
    }
    if (tid < 18) s_R1s[tid] = lr1W[8*18 + tid];
    for (int i = tid; i < 27; i += 256) {
        int p = i/9, k = i%9;
        ((float2*)&s_R2[p][0])[k] = make_float2(lr2W[(2*p)*9+k], lr2W[(2*p+1)*9+k]);
    }
    if (tid < 9) s_R2s[tid] = lr2W[6*9 + tid];
    if (tid < 4) ((float2*)s_R1b)[tid] = make_float2(lr1b[2*tid], lr1b[2*tid+1]);
    if (tid == 4) s_R1bs = lr1b[8];
    if (tid < 3) ((float2*)s_R2b)[tid] = make_float2(lr2b[2*tid], lr2b[2*tid+1]);
    if (tid == 3) s_R2bs = lr2b[6];
    __syncthreads();

    const int half = N * MM;
    const int id = blockIdx.x * 256 + tid;
    if (id >= TT * half) return;
    const int t = id / half;
    const int nm = id - t * half;
    const int n = nm / MM, m = nm - n*MM;
    const int nr0 = numrec[(size_t)n * TT];
    float* po = out_p + ((size_t)n*(TT*MM) + t*MM + m) * 7;

    if (m >= nr0) {
        #pragma unroll
        for (int k = 0; k < 7; k++) po[k] = 0.0f;
        return;
    }

    float o18[18];
    load9(o18,     g_lstm[0] + ((size_t)t*half + nm)*12);
    load9(o18 + 9, g_lstm[1] + ((size_t)t*half + nm)*12);
    u64 o2[18];
    #pragma unroll
    for (int k = 0; k < 18; k++) o2[k] = pk(o18[k], o18[k]);

    float q[9];
    #pragma unroll
    for (int p = 0; p < 4; p++) {
        u64 acc = s_R1b[p];
        #pragma unroll
        for (int k = 0; k < 18; k++) acc = ffma2(s_R1[p][k], o2[k], acc);
        float a, b; upk(a, b, acc);
        q[2*p]   = fmaxf(a, 0.0f);
        q[2*p+1] = fmaxf(b, 0.0f);
    }
    {
        float acc = s_R1bs;
        #pragma unroll
        for (int k = 0; k < 18; k++) acc = fmaf(s_R1s[k], o18[k], acc);
        q[8] = fmaxf(acc, 0.0f);
    }
    u64 q2[9];
    #pragma unroll
    for (int k = 0; k < 9; k++) q2[k] = pk(q[k], q[k]);

    float o7[7];
    #pragma unroll
    for (int p = 0; p < 3; p++) {
        u64 acc = s_R2b[p];
        #pragma unroll
        for (int k = 0; k < 9; k++) acc = ffma2(s_R2[p][k], q2[k], acc);
        upk(o7[2*p], o7[2*p+1], acc);
    }
    {
        float acc = s_R2bs;
        #pragma unroll
        for (int k = 0; k < 9; k++) acc = fmaf(s_R2s[k], q[k], acc);
        o7[6] = acc;
    }

    #pragma unroll
    for (int k = 0; k < 7; k++) po[k] = o7[k];
}

extern "C" void kernel_launch(void* const* d_in, const int* in_sizes, int n_in,
                              void* d_out, int out_size)
{
    const float* nf    = (const float*)d_in[0];
    const float* pos   = (const float*)d_in[1];
    const float* attm  = (const float*)d_in[2];
    const float* msgW  = (const float*)d_in[3];
    const float* msgb  = (const float*)d_in[4];
    const float* gWih  = (const float*)d_in[5];
    const float* gWhh  = (const float*)d_in[6];
    const float* gbih  = (const float*)d_in[7];
    const float* gbhh  = (const float*)d_in[8];
    const float* ro1W  = (const float*)d_in[9];
    const float* ro1b  = (const float*)d_in[10];
    const float* ro2W  = (const float*)d_in[11];
    const float* ro2b  = (const float*)d_in[12];
    const float* lfWih = (const float*)d_in[13];
    const float* lfWhh = (const float*)d_in[14];
    const float* lfbih = (const float*)d_in[15];
    const float* lfbhh = (const float*)d_in[16];
    const float* lbWih = (const float*)d_in[17];
    const float* lbWhh = (const float*)d_in[18];
    const float* lbbih = (const float*)d_in[19];
    const float* lbbhh = (const float*)d_in[20];
    const float* lr1W  = (const float*)d_in[21];
    const float* lr1b  = (const float*)d_in[22];
    const float* lr2W  = (const float*)d_in[23];
    const float* lr2b  = (const float*)d_in[24];
    const int*   nrec  = (const int*)d_in[25];

    const int N = in_sizes[25] / TT;
    float* out = (float*)d_out;
    float* out_p  = out;                              // pred_label
    float* out_p0 = out + (size_t)N * TT * MM * 7;    // pred_label0

    const int grid1 = (N*TT + 31) / 32;
    const int Wdw   = (N*MM + 5) / 6;
    const int grid2 = (2*Wdw + 3) / 4;
    const int grid3 = (N*TT*MM + 255) / 256;

    k_compact<<<1, 1024>>>(nrec, N);                   // launch #1
    k1_gru<<<grid1, 192>>>(nf, pos, attm, msgW, msgb, gWih, gWhh, gbih, gbhh,
                           ro1W, ro1b, ro2W, ro2b, nrec, out_p0, N);   // #2
    k2_lstm<<<grid2, 128>>>(lfWih, lfWhh, lfbih, lfbhh,
                            lbWih, lbWhh, lbbih, lbbhh, N);            // #3
    k3_readout<<<grid3, 256>>>(lr1W, lr1b, lr2W, lr2b, nrec, out_p, N); // #4 (profiled)
}